// round 2
// baseline (speedup 1.0000x reference)
#include <cuda_runtime.h>
#include <math.h>

#define D 128
#define H 4
#define NMAX 500000
#define BMAX 8192

// Scratch (no allocs allowed): packed per-node head scores + segment starts.
__device__ float4 g_scores[NMAX];
__device__ int    g_seg_start[BMAX + 1];

// ---------------------------------------------------------------------------
// Dtype-agnostic id accessor: batch_indices may be int32 (JAX x64-disabled
// downgrades jnp.int64) or genuine int64. Detect via a high-word probe.
// ---------------------------------------------------------------------------
__device__ __forceinline__ bool ids_are_64bit(const int* ids32, int N) {
    // odd index near the end, valid for both layouts (j < N)
    int j = ((N - 1) & 1) ? (N - 1) : (N - 2);
    if (j < 0) j = 0;
    // int64 data: ids32[odd] is the high word of a small nonneg value -> 0
    // int32 data: a late sorted id -> almost surely != 0
    return ids32[j] == 0;
}

__device__ __forceinline__ int get_id(const void* ids, bool is64, int n, int B) {
    int v = is64 ? (int)((const long long*)ids)[n] : ((const int*)ids)[n];
    return v < 0 ? 0 : (v >= B ? B - 1 : v);
}

// ---------------------------------------------------------------------------
// Kernel 0: segment boundaries from sorted batch indices.
// ---------------------------------------------------------------------------
__global__ void k_bounds(const void* __restrict__ ids, int N, int B) {
    int n = blockIdx.x * blockDim.x + threadIdx.x;
    if (n >= N) return;
    bool is64 = ids_are_64bit((const int*)ids, N);
    int id = get_id(ids, is64, n, B);
    if (n == 0) {
        for (int bb = 0; bb <= id; bb++) g_seg_start[bb] = 0;
    } else {
        int prev = get_id(ids, is64, n - 1, B);
        for (int bb = prev + 1; bb <= id; bb++) g_seg_start[bb] = n;
    }
    if (n == N - 1) {
        for (int bb = id + 1; bb <= B; bb++) g_seg_start[bb] = N;
    }
}

// ---------------------------------------------------------------------------
// Kernel 1: scores[n][h] = (x[n]·W[h] + b[h]) / T.  Warp per node, float4 IO.
// ---------------------------------------------------------------------------
__global__ void __launch_bounds__(256) k_scores(
    const float* __restrict__ x, const float* __restrict__ W,
    const float* __restrict__ bias, const float* __restrict__ temp, int N)
{
    __shared__ float4 Ws[H][D / 4];   // W[h][d] as float4
    __shared__ float  bs[H];
    __shared__ float  tinv;
    int tid = threadIdx.x;
    for (int i = tid; i < H * D / 4; i += blockDim.x) {
        Ws[i / (D / 4)][i % (D / 4)] = ((const float4*)W)[i];
    }
    if (tid < H) bs[tid] = bias[tid];
    if (tid == 0) tinv = 1.0f / temp[0];
    __syncthreads();

    int warp = tid >> 5, lane = tid & 31;
    int n = blockIdx.x * 8 + warp;
    if (n >= N) return;

    float4 xv = ((const float4*)(x + (size_t)n * D))[lane];
    float s0, s1, s2, s3;
    {
        float4 w0 = Ws[0][lane], w1 = Ws[1][lane], w2 = Ws[2][lane], w3 = Ws[3][lane];
        s0 = xv.x * w0.x + xv.y * w0.y + xv.z * w0.z + xv.w * w0.w;
        s1 = xv.x * w1.x + xv.y * w1.y + xv.z * w1.z + xv.w * w1.w;
        s2 = xv.x * w2.x + xv.y * w2.y + xv.z * w2.z + xv.w * w2.w;
        s3 = xv.x * w3.x + xv.y * w3.y + xv.z * w3.z + xv.w * w3.w;
    }
    #pragma unroll
    for (int off = 16; off > 0; off >>= 1) {
        s0 += __shfl_xor_sync(0xFFFFFFFFu, s0, off);
        s1 += __shfl_xor_sync(0xFFFFFFFFu, s1, off);
        s2 += __shfl_xor_sync(0xFFFFFFFFu, s2, off);
        s3 += __shfl_xor_sync(0xFFFFFFFFu, s3, off);
    }
    if (lane == 0) {
        float4 sc;
        sc.x = (s0 + bs[0]) * tinv;
        sc.y = (s1 + bs[1]) * tinv;
        sc.z = (s2 + bs[2]) * tinv;
        sc.w = (s3 + bs[3]) * tinv;
        g_scores[n] = sc;
    }
}

// ---------------------------------------------------------------------------
// Kernel 2: per-segment softmax stats + attn output + pooled (mean over heads
// folded into a per-node scalar weight before touching x).
// One 128-thread block per segment; thread t owns output dim d=t.
// ---------------------------------------------------------------------------
__global__ void __launch_bounds__(128) k_pool(
    const float* __restrict__ x,
    float* __restrict__ out_pooled,   // [B, D]
    float* __restrict__ out_attn,     // [H, N]
    int N)
{
    int b = blockIdx.x;
    int start = g_seg_start[b];
    int end   = g_seg_start[b + 1];
    int len   = end - start;
    int tid   = threadIdx.x;
    int lane  = tid & 31, warp = tid >> 5;

    __shared__ float4 wred[4];
    __shared__ float  attn_s[H][128];
    __shared__ float  w_s[128];

    // ---- Phase 1a: segment max per head ----
    float4 m = make_float4(-INFINITY, -INFINITY, -INFINITY, -INFINITY);
    for (int i = tid; i < len; i += 128) {
        float4 s = g_scores[start + i];
        m.x = fmaxf(m.x, s.x); m.y = fmaxf(m.y, s.y);
        m.z = fmaxf(m.z, s.z); m.w = fmaxf(m.w, s.w);
    }
    #pragma unroll
    for (int off = 16; off > 0; off >>= 1) {
        m.x = fmaxf(m.x, __shfl_xor_sync(0xFFFFFFFFu, m.x, off));
        m.y = fmaxf(m.y, __shfl_xor_sync(0xFFFFFFFFu, m.y, off));
        m.z = fmaxf(m.z, __shfl_xor_sync(0xFFFFFFFFu, m.z, off));
        m.w = fmaxf(m.w, __shfl_xor_sync(0xFFFFFFFFu, m.w, off));
    }
    if (lane == 0) wred[warp] = m;
    __syncthreads();
    float4 M;
    {
        float4 a = wred[0], c = wred[1], e = wred[2], g = wred[3];
        M.x = fmaxf(fmaxf(a.x, c.x), fmaxf(e.x, g.x));
        M.y = fmaxf(fmaxf(a.y, c.y), fmaxf(e.y, g.y));
        M.z = fmaxf(fmaxf(a.z, c.z), fmaxf(e.z, g.z));
        M.w = fmaxf(fmaxf(a.w, c.w), fmaxf(e.w, g.w));
    }
    __syncthreads();

    // ---- Phase 1b: segment sum of exp ----
    float4 sum = make_float4(0.f, 0.f, 0.f, 0.f);
    for (int i = tid; i < len; i += 128) {
        float4 s = g_scores[start + i];
        sum.x += __expf(s.x - M.x);
        sum.y += __expf(s.y - M.y);
        sum.z += __expf(s.z - M.z);
        sum.w += __expf(s.w - M.w);
    }
    #pragma unroll
    for (int off = 16; off > 0; off >>= 1) {
        sum.x += __shfl_xor_sync(0xFFFFFFFFu, sum.x, off);
        sum.y += __shfl_xor_sync(0xFFFFFFFFu, sum.y, off);
        sum.z += __shfl_xor_sync(0xFFFFFFFFu, sum.z, off);
        sum.w += __shfl_xor_sync(0xFFFFFFFFu, sum.w, off);
    }
    if (lane == 0) wred[warp] = sum;
    __syncthreads();
    float4 R;
    {
        float4 a = wred[0], c = wred[1], e = wred[2], g = wred[3];
        float sx = a.x + c.x + e.x + g.x;
        float sy = a.y + c.y + e.y + g.y;
        float sz = a.z + c.z + e.z + g.z;
        float sw = a.w + c.w + e.w + g.w;
        R.x = (len > 0) ? 1.0f / sx : 0.f;
        R.y = (len > 0) ? 1.0f / sy : 0.f;
        R.z = (len > 0) ? 1.0f / sz : 0.f;
        R.w = (len > 0) ? 1.0f / sw : 0.f;
    }

    // ---- Phase 2: per-chunk attn + pooled accumulation ----
    float acc = 0.f;
    for (int c = 0; c < len; c += 128) {
        int cl = min(128, len - c);
        __syncthreads();
        if (tid < cl) {
            float4 s = g_scores[start + c + tid];
            float e0 = __expf(s.x - M.x) * R.x;
            float e1 = __expf(s.y - M.y) * R.y;
            float e2 = __expf(s.z - M.z) * R.z;
            float e3 = __expf(s.w - M.w) * R.w;
            attn_s[0][tid] = e0; attn_s[1][tid] = e1;
            attn_s[2][tid] = e2; attn_s[3][tid] = e3;
            w_s[tid] = 0.25f * (e0 + e1 + e2 + e3);
        }
        __syncthreads();
        // coalesced attn writes: per head, contiguous node range
        if (cl == 128) {
            #pragma unroll
            for (int h = 0; h < H; h++)
                out_attn[(size_t)h * N + start + c + tid] = attn_s[h][tid];
        } else {
            for (int idx = tid; idx < H * cl; idx += 128) {
                int h = idx / cl, j = idx - h * cl;
                out_attn[(size_t)h * N + start + c + j] = attn_s[h][j];
            }
        }
        // pooled: thread t owns dim t; consecutive rows, fully coalesced
        const float* xb = x + (size_t)(start + c) * D + tid;
        int j = 0;
        for (; j + 4 <= cl; j += 4) {
            float v0 = xb[(size_t)(j + 0) * D];
            float v1 = xb[(size_t)(j + 1) * D];
            float v2 = xb[(size_t)(j + 2) * D];
            float v3 = xb[(size_t)(j + 3) * D];
            acc += w_s[j] * v0 + w_s[j + 1] * v1 + w_s[j + 2] * v2 + w_s[j + 3] * v3;
        }
        for (; j < cl; j++) acc += w_s[j] * xb[(size_t)j * D];
    }
    out_pooled[(size_t)b * D + tid] = acc;
}

// ---------------------------------------------------------------------------
extern "C" void kernel_launch(void* const* d_in, const int* in_sizes, int n_in,
                              void* d_out, int out_size)
{
    const float* x    = (const float*)d_in[0];
    const void*  ids  = d_in[1];
    const float* W    = (const float*)d_in[2];
    const float* bias = (const float*)d_in[3];
    const float* temp = (const float*)d_in[4];

    int N = in_sizes[1];                       // node count
    int B = (out_size - H * N) / D;            // segment count from output size
    if (B < 1) B = 1;
    if (B > BMAX) B = BMAX;

    float* out_pooled = (float*)d_out;                       // [B, D]
    float* out_attn   = (float*)d_out + (size_t)B * D;       // [H, N]

    k_bounds<<<(N + 255) / 256, 256>>>(ids, N, B);
    k_scores<<<(N + 7) / 8, 256>>>(x, W, bias, temp, N);
    k_pool<<<B, 128>>>(x, out_pooled, out_attn, N);
}